// round 14
// baseline (speedup 1.0000x reference)
#include <cuda_runtime.h>
#include <math.h>

#define TPB 128
#define NEG_INF (-3.402823466e+38f)
#define LOG2E 1.4426950408889634f

__device__ __forceinline__ float ex2(float x) {
    float r;
    asm("ex2.approx.f32 %0, %1;" : "=f"(r) : "f"(x));
    return r;
}

__global__ __launch_bounds__(TPB, 9) void dfine_lqe_kernel(
    const float* __restrict__ scores,   // (tokens, 80)
    const float* __restrict__ pc,       // (tokens, 132)
    const float* __restrict__ W1,       // (20, 64)
    const float* __restrict__ b1,       // (64,)
    const float* __restrict__ W2,       // (64, 1)
    const float* __restrict__ b2,       // (1,)
    float* __restrict__ out,            // (tokens, 80)
    int tokens)
{
    __shared__ float sW1e[64 * 16];     // folded W1, row-major [j][16] (64B rows, uniform broadcast)
    __shared__ float sB1[64];
    __shared__ float sW2[64];
    __shared__ float sQ[TPB];

    const int tid = threadIdx.x;
    const int t0  = blockIdx.x * TPB;
    const int ntb = min(TPB, tokens - t0);

    // ---- stage effective weights: W1e[j][4g+k] = W1[5g+k][j] + 0.25*W1[5g+4][j] ----
    #pragma unroll 2
    for (int i = tid; i < 1024; i += TPB) {
        int j = i >> 4;
        int d = i & 15;
        int g = d >> 2, k = d & 3;
        sW1e[i] = W1[(g * 5 + k) * 64 + j] + 0.25f * W1[(g * 5 + 4) * 64 + j];
    }
    if (tid < 64) {
        sB1[tid] = b1[tid];
        sW2[tid] = W2[tid];
    }
    __syncthreads();

    if (tid < ntb) {
        const int token = t0 + tid;
        const float4* xp4 = reinterpret_cast<const float4*>(pc) + (size_t)token * 33;

        // running top-4 per group (log2 domain; scaling is monotone) + unshifted 2^x sums
        float m0[4], m1[4], m2[4], m3[4], sum[4];
        #pragma unroll
        for (int g = 0; g < 4; g++) {
            m0[g] = NEG_INF; m1[g] = NEG_INF; m2[g] = NEG_INF; m3[g] = NEG_INF;
            sum[g] = 0.0f;
        }

        // single fully-unrolled streaming pass: each vec4 loaded exactly once
        #pragma unroll
        for (int v = 0; v < 33; v++) {
            float4 t = xp4[v];
            #pragma unroll
            for (int e = 0; e < 4; e++) {
                const int pos = 4 * v + e;          // 0..131
                const int g   = pos / 33;           // compile-time group id
                float raw = (e == 0) ? t.x : (e == 1) ? t.y : (e == 2) ? t.z : t.w;
                float val = raw * LOG2E;            // softmax(x) == softmax_2(x*log2e)
                float a1 = fminf(m0[g], val); m0[g] = fmaxf(m0[g], val);
                float a2 = fminf(m1[g], a1);  m1[g] = fmaxf(m1[g], a1);
                float a3 = fminf(m2[g], a2);  m2[g] = fmaxf(m2[g], a2);
                m3[g] = fmaxf(m3[g], a3);
                sum[g] += ex2(val);
            }
        }

        // top-4 probabilities: p_k = 2^{m_k} / sum
        float stat[16];
        #pragma unroll
        for (int g = 0; g < 4; g++) {
            float inv = 1.0f / sum[g];
            stat[g * 4 + 0] = ex2(m0[g]) * inv;
            stat[g * 4 + 1] = ex2(m1[g]) * inv;
            stat[g * 4 + 2] = ex2(m2[g]) * inv;
            stat[g * 4 + 3] = ex2(m3[g]) * inv;
        }

        // ---- tiny MLP (mean folded): q = W2 . relu(W1e^T p + b1) + b2 ----
        float q = b2[0];
        #pragma unroll 4
        for (int j = 0; j < 64; j++) {
            const float4* w4 = reinterpret_cast<const float4*>(&sW1e[j * 16]);  // warp-uniform
            float acc = sB1[j];
            float4 wa = w4[0], wb = w4[1], wc = w4[2], wd = w4[3];
            acc = fmaf(stat[0],  wa.x, acc); acc = fmaf(stat[1],  wa.y, acc);
            acc = fmaf(stat[2],  wa.z, acc); acc = fmaf(stat[3],  wa.w, acc);
            acc = fmaf(stat[4],  wb.x, acc); acc = fmaf(stat[5],  wb.y, acc);
            acc = fmaf(stat[6],  wb.z, acc); acc = fmaf(stat[7],  wb.w, acc);
            acc = fmaf(stat[8],  wc.x, acc); acc = fmaf(stat[9],  wc.y, acc);
            acc = fmaf(stat[10], wc.z, acc); acc = fmaf(stat[11], wc.w, acc);
            acc = fmaf(stat[12], wd.x, acc); acc = fmaf(stat[13], wd.y, acc);
            acc = fmaf(stat[14], wd.z, acc); acc = fmaf(stat[15], wd.w, acc);
            q = fmaf(fmaxf(acc, 0.0f), sW2[j], q);
        }
        sQ[tid] = q;
    }
    __syncthreads();

    // ---- coalesced epilogue: out = scores + q[token], float4 ----
    {
        const float4* sc4  = reinterpret_cast<const float4*>(scores) + (size_t)t0 * 20;
        float4*       out4 = reinterpret_cast<float4*>(out) + (size_t)t0 * 20;
        const int nvec = ntb * 20;
        #pragma unroll 4
        for (int i = tid; i < nvec; i += TPB) {
            int row = i / 20;
            float4 s = sc4[i];
            float qq = sQ[row];
            s.x += qq; s.y += qq; s.z += qq; s.w += qq;
            out4[i] = s;
        }
    }
}

extern "C" void kernel_launch(void* const* d_in, const int* in_sizes, int n_in,
                              void* d_out, int out_size)
{
    const float* scores = (const float*)d_in[0];
    const float* pc     = (const float*)d_in[1];
    const float* W1     = (const float*)d_in[2];
    const float* b1     = (const float*)d_in[3];
    const float* W2     = (const float*)d_in[4];
    const float* b2     = (const float*)d_in[5];
    float* out = (float*)d_out;

    const int tokens = in_sizes[1] / 132;
    const int nblocks = (tokens + TPB - 1) / TPB;

    dfine_lqe_kernel<<<nblocks, TPB>>>(scores, pc, W1, b1, W2, b2, out, tokens);
}